// round 2
// baseline (speedup 1.0000x reference)
#include <cuda_runtime.h>
#include <cuda_bf16.h>
#include <math.h>

// ---------------- problem constants ----------------
#define MM   32      // state dim m
#define NN   16      // obs dim n
#define BB   256     // batch
#define TT   8       // time steps
#define HQ   1024    // m*m
#define HS   256     // n*n
#define D_Q_IN   160      // m*IN_MULT
#define D_SIG_IN 1184     // HQ + 160
#define D_S_IN   416      // 256 + 160
#define D_FC2_IN 1280     // HQ + HS
#define D_FC2_H  2560

// ---------------- device scratch (no allocations allowed) ----------------
__device__ float g_zQ  [BB * 4 * HQ];
__device__ float g_zSig[BB * 4 * HQ];
__device__ float g_zS  [BB * 4 * HS];
__device__ float g_hQ  [BB * HQ];
__device__ float g_cQ  [BB * HQ];
__device__ float g_hSig[BB * HQ];
__device__ float g_cSig[BB * HQ];
__device__ float g_hS  [BB * HS];
__device__ float g_cS  [BB * HS];
__device__ float g_out5[BB * D_Q_IN];
__device__ float g_out6[BB * D_Q_IN];
__device__ float g_out7[BB * D_Q_IN];
__device__ float g_out1[BB * HS];
__device__ float g_a2  [BB * D_FC2_H];
__device__ float g_kvec[BB * NN * MM];
__device__ float g_xprior[2][BB * MM];
__device__ float g_dy   [BB * NN];
__device__ float g_fwupd [BB * MM];
__device__ float g_fwevol[BB * MM];
__device__ float g_obscat[BB * 2 * NN];
__device__ float g_yprev0[BB * NN];

// ---------------- init: zero LSTM states, y_prev0 = tanh(x0[:, :16]) ----------------
__global__ void init_kernel(const float* __restrict__ x0,
                            float* __restrict__ yprev0,
                            float* hQ, float* cQ, float* hSig, float* cSig,
                            float* hS, float* cS)
{
    int idx = blockIdx.x * blockDim.x + threadIdx.x;
    if (idx < BB * HQ) { hQ[idx] = 0.f; cQ[idx] = 0.f; hSig[idx] = 0.f; cSig[idx] = 0.f; }
    if (idx < BB * HS) { hS[idx] = 0.f; cS[idx] = 0.f; }
    if (idx < BB * NN) {
        int b = idx / NN, n = idx % NN;
        yprev0[idx] = tanhf(x0[b * MM + n]);
    }
}

// ---------------- per-step prologue: f_dyn, h_obs, 4 normalized features ----------------
// grid = BB blocks, 32 threads (one warp per batch row)
__global__ void pre_kernel(const float* __restrict__ x_post,
                           const float* __restrict__ x_post_prev,
                           const float* __restrict__ x_prior_prev,
                           const float* __restrict__ y_t,
                           const float* __restrict__ y_prev,
                           float* __restrict__ x_prior,
                           float* __restrict__ dy_buf,
                           float* __restrict__ fw_upd,
                           float* __restrict__ fw_evol,
                           float* __restrict__ obs_cat)
{
    int b = blockIdx.x;
    int lane = threadIdx.x;  // 0..31

    float xp   = x_post[b * MM + lane];
    float xpp  = x_post_prev[b * MM + lane];
    float xprp = x_prior_prev[b * MM + lane];

    float xpr = xp + 0.1f * sinf(xp);          // f_dyn
    x_prior[b * MM + lane] = xpr;

    float de = xp - xpp;    // fw_evol raw
    float du = xp - xprp;   // fw_upd raw
    float se = de * de, su = du * du;
    #pragma unroll
    for (int o = 16; o > 0; o >>= 1) {
        se += __shfl_xor_sync(0xffffffffu, se, o);
        su += __shfl_xor_sync(0xffffffffu, su, o);
    }
    fw_evol[b * MM + lane] = de / fmaxf(sqrtf(se), 1e-12f);
    fw_upd [b * MM + lane] = du / fmaxf(sqrtf(su), 1e-12f);

    // obs features (first 16 lanes carry data, upper lanes contribute zeros)
    float y     = (lane < NN) ? y_t[b * NN + lane]    : 0.f;
    float ypv   = (lane < NN) ? y_prev[b * NN + lane] : 0.f;
    float ypred = (lane < NN) ? tanhf(xpr)            : 0.f;  // h_obs(x_prior)
    float d1 = y - ypv;      // obs_diff raw
    float d2 = y - ypred;    // innovation raw (also KF dy)
    if (lane < NN) dy_buf[b * NN + lane] = d2;
    float s1 = d1 * d1, s2 = d2 * d2;
    #pragma unroll
    for (int o = 16; o > 0; o >>= 1) {
        s1 += __shfl_xor_sync(0xffffffffu, s1, o);
        s2 += __shfl_xor_sync(0xffffffffu, s2, o);
    }
    if (lane < NN) {
        obs_cat[b * 2 * NN + lane]      = d1 / fmaxf(sqrtf(s1), 1e-12f);
        obs_cat[b * 2 * NN + NN + lane] = d2 / fmaxf(sqrtf(s2), 1e-12f);
    }
}

// ---------------- fused fc5 / fc6 / fc7 (all [160,32] + relu) ----------------
// grid = (BB, 3), block = 160
__global__ void fc_small_kernel(const float* __restrict__ in_upd,
                                const float* __restrict__ in_evol,
                                const float* __restrict__ in_obs,
                                const float* __restrict__ w5, const float* __restrict__ b5,
                                const float* __restrict__ w6, const float* __restrict__ b6,
                                const float* __restrict__ w7, const float* __restrict__ b7,
                                float* __restrict__ out5,
                                float* __restrict__ out6,
                                float* __restrict__ out7)
{
    int which = blockIdx.y;
    const float* X = (which == 0) ? in_upd : (which == 1) ? in_evol : in_obs;
    const float* W = (which == 0) ? w5     : (which == 1) ? w6      : w7;
    const float* Bv= (which == 0) ? b5     : (which == 1) ? b6      : b7;
    float* O       = (which == 0) ? out5   : (which == 1) ? out6    : out7;

    int b = blockIdx.x;
    __shared__ float xs[32];
    if (threadIdx.x < 32) xs[threadIdx.x] = X[b * 32 + threadIdx.x];
    __syncthreads();

    int o = threadIdx.x;  // 0..159
    float acc = Bv[o];
    const float* wr = W + o * 32;
    #pragma unroll
    for (int k = 0; k < 32; k++) acc += xs[k] * wr[k];
    O[b * D_Q_IN + o] = fmaxf(acc, 0.f);
}

// ---------------- generic multi-segment SGEMM ----------------
// Z[b, o] = act( sum_s X_s[b,:] . W_s[o,:] + bias0[o] (+ bias1[o]) )
// W_s is row-major [O, ldw_s], pointer may carry a column offset (for concat inputs).
struct GSeg {
    const float* X;   // [BB, K] contiguous
    const float* W;   // row-major, row stride ldw
    int K;
    int ldw;
};

__global__ void __launch_bounds__(256) gemm_kernel(
    GSeg s0, GSeg s1, GSeg s2, int nseg,
    const float* __restrict__ bias0, const float* __restrict__ bias1,
    float* __restrict__ Z, int Nout, int act)
{
    __shared__ float As[16][64];   // As[k][m]  (activations)
    __shared__ float Bs[16][64];   // Bs[k][n]  (weights^T)

    int tid = threadIdx.x;
    int tx = tid & 15;        // output-col quad
    int ty = tid >> 4;        // batch-row quad
    int row0 = blockIdx.y * 64;
    int col0 = blockIdx.x * 64;

    float acc[4][4];
    #pragma unroll
    for (int i = 0; i < 4; i++)
        #pragma unroll
        for (int j = 0; j < 4; j++) acc[i][j] = 0.f;

    #pragma unroll
    for (int s = 0; s < 3; s++) {
        if (s >= nseg) break;
        const GSeg seg = (s == 0) ? s0 : (s == 1) ? s1 : s2;
        const float* __restrict__ X = seg.X;
        const float* __restrict__ W = seg.W;
        const int K = seg.K, ldw = seg.ldw;

        for (int k0 = 0; k0 < K; k0 += 16) {
            #pragma unroll
            for (int i = 0; i < 4; i++) {
                int idx = tid + i * 256;       // 0..1023
                int m = idx >> 4;
                int k = idx & 15;
                int kk = k0 + k;
                As[k][m] = (kk < K) ? X[(row0 + m) * K + kk] : 0.f;
                Bs[k][m] = (kk < K) ? W[(size_t)(col0 + m) * ldw + kk] : 0.f;
            }
            __syncthreads();
            #pragma unroll
            for (int k = 0; k < 16; k++) {
                float4 av = *reinterpret_cast<const float4*>(&As[k][ty * 4]);
                float4 bv = *reinterpret_cast<const float4*>(&Bs[k][tx * 4]);
                float a[4] = {av.x, av.y, av.z, av.w};
                float bb[4] = {bv.x, bv.y, bv.z, bv.w};
                #pragma unroll
                for (int i = 0; i < 4; i++)
                    #pragma unroll
                    for (int j = 0; j < 4; j++)
                        acc[i][j] += a[i] * bb[j];
            }
            __syncthreads();
        }
    }

    #pragma unroll
    for (int i = 0; i < 4; i++) {
        int r = row0 + ty * 4 + i;
        #pragma unroll
        for (int j = 0; j < 4; j++) {
            int c = col0 + tx * 4 + j;
            float v = acc[i][j];
            if (bias0) v += bias0[c];
            if (bias1) v += bias1[c];
            if (act) v = fmaxf(v, 0.f);
            Z[(size_t)r * Nout + c] = v;
        }
    }
}

// ---------------- LSTM pointwise gates (torch order i,f,g,o) ----------------
__global__ void lstm_gate_kernel(const float* __restrict__ Z,
                                 float* __restrict__ h, float* __restrict__ c, int H)
{
    int idx = blockIdx.x * blockDim.x + threadIdx.x;
    if (idx >= BB * H) return;
    int b = idx / H, j = idx % H;
    const float* z = Z + (size_t)b * 4 * H;
    float gi = z[j], gf = z[H + j], gg = z[2 * H + j], go = z[3 * H + j];
    float si = 1.f / (1.f + expf(-gi));
    float sf = 1.f / (1.f + expf(-gf));
    float so = 1.f / (1.f + expf(-go));
    float cn = sf * c[idx] + si * tanhf(gg);
    c[idx] = cn;
    h[idx] = so * tanhf(cn);
}

// ---------------- KF update: x_post = x_prior + K @ dy ----------------
// grid = BB, block = 32
__global__ void update_kernel(const float* __restrict__ x_prior,
                              const float* __restrict__ kvec,
                              const float* __restrict__ dy,
                              float* __restrict__ out)
{
    int b = blockIdx.x;
    int m = threadIdx.x;
    __shared__ float dys[NN];
    if (m < NN) dys[m] = dy[b * NN + m];
    __syncthreads();
    float acc = x_prior[b * MM + m];
    const float* Kr = kvec + (size_t)b * MM * NN + m * NN;
    #pragma unroll
    for (int n = 0; n < NN; n++) acc += Kr[n] * dys[n];
    out[b * MM + m] = acc;
}

// ---------------- host orchestration ----------------
extern "C" void kernel_launch(void* const* d_in, const int* in_sizes, int n_in,
                              void* d_out, int out_size)
{
    const float* Y       = (const float*)d_in[0];
    const float* x0      = (const float*)d_in[1];
    const float* Wq_ih   = (const float*)d_in[2];
    const float* Wq_hh   = (const float*)d_in[3];
    const float* bq_ih   = (const float*)d_in[4];
    const float* bq_hh   = (const float*)d_in[5];
    const float* Wsig_ih = (const float*)d_in[6];
    const float* Wsig_hh = (const float*)d_in[7];
    const float* bsig_ih = (const float*)d_in[8];
    const float* bsig_hh = (const float*)d_in[9];
    const float* Ws_ih   = (const float*)d_in[10];
    const float* Ws_hh   = (const float*)d_in[11];
    const float* bs_ih   = (const float*)d_in[12];
    const float* bs_hh   = (const float*)d_in[13];
    const float* fc1_w   = (const float*)d_in[14];
    const float* fc1_b   = (const float*)d_in[15];
    const float* fc2a_w  = (const float*)d_in[16];
    const float* fc2a_b  = (const float*)d_in[17];
    const float* fc2b_w  = (const float*)d_in[18];
    const float* fc2b_b  = (const float*)d_in[19];
    const float* fc5_w   = (const float*)d_in[20];
    const float* fc5_b   = (const float*)d_in[21];
    const float* fc6_w   = (const float*)d_in[22];
    const float* fc6_b   = (const float*)d_in[23];
    const float* fc7_w   = (const float*)d_in[24];
    const float* fc7_b   = (const float*)d_in[25];

    float* out = (float*)d_out;   // [T, B, M, 1]

    float *zQ, *zSig, *zS, *hQ, *cQ, *hSig, *cSig, *hS, *cS;
    float *out5, *out6, *out7, *out1, *a2, *kvec;
    float *xprior0, *xprior1, *dy, *fwupd, *fwevol, *obscat, *yprev0;
    cudaGetSymbolAddress((void**)&zQ,    g_zQ);
    cudaGetSymbolAddress((void**)&zSig,  g_zSig);
    cudaGetSymbolAddress((void**)&zS,    g_zS);
    cudaGetSymbolAddress((void**)&hQ,    g_hQ);
    cudaGetSymbolAddress((void**)&cQ,    g_cQ);
    cudaGetSymbolAddress((void**)&hSig,  g_hSig);
    cudaGetSymbolAddress((void**)&cSig,  g_cSig);
    cudaGetSymbolAddress((void**)&hS,    g_hS);
    cudaGetSymbolAddress((void**)&cS,    g_cS);
    cudaGetSymbolAddress((void**)&out5,  g_out5);
    cudaGetSymbolAddress((void**)&out6,  g_out6);
    cudaGetSymbolAddress((void**)&out7,  g_out7);
    cudaGetSymbolAddress((void**)&out1,  g_out1);
    cudaGetSymbolAddress((void**)&a2,    g_a2);
    cudaGetSymbolAddress((void**)&kvec,  g_kvec);
    cudaGetSymbolAddress((void**)&xprior0, g_xprior);
    xprior1 = xprior0 + BB * MM;
    cudaGetSymbolAddress((void**)&dy,    g_dy);
    cudaGetSymbolAddress((void**)&fwupd, g_fwupd);
    cudaGetSymbolAddress((void**)&fwevol,g_fwevol);
    cudaGetSymbolAddress((void**)&obscat,g_obscat);
    cudaGetSymbolAddress((void**)&yprev0,g_yprev0);

    float* xprior_buf[2] = {xprior0, xprior1};

    const GSeg nil = {nullptr, nullptr, 0, 0};

    init_kernel<<<(BB * HQ + 255) / 256, 256>>>(x0, yprev0, hQ, cQ, hSig, cSig, hS, cS);

    for (int t = 0; t < TT; t++) {
        const float* x_post      = (t == 0) ? x0 : out + (size_t)(t - 1) * BB * MM;
        const float* x_post_prev = (t <= 1) ? x0 : out + (size_t)(t - 2) * BB * MM;
        const float* x_prior_prev= (t == 0) ? x0 : xprior_buf[(t - 1) & 1];
        const float* y_t         = Y + (size_t)t * BB * NN;
        const float* y_prev      = (t == 0) ? yprev0 : Y + (size_t)(t - 1) * BB * NN;
        float* x_prior           = xprior_buf[t & 1];

        pre_kernel<<<BB, 32>>>(x_post, x_post_prev, x_prior_prev, y_t, y_prev,
                               x_prior, dy, fwupd, fwevol, obscat);

        fc_small_kernel<<<dim3(BB, 3), 160>>>(fwupd, fwevol, obscat,
                                              fc5_w, fc5_b, fc6_w, fc6_b, fc7_w, fc7_b,
                                              out5, out6, out7);

        // LSTM Q: z = out5 @ Wq_ih^T + hQ @ Wq_hh^T + bq_ih + bq_hh
        {
            GSeg a = {out5, Wq_ih, D_Q_IN, D_Q_IN};
            GSeg b = {hQ,   Wq_hh, HQ,     HQ};
            gemm_kernel<<<dim3(4 * HQ / 64, BB / 64), 256>>>(a, b, nil, 2, bq_ih, bq_hh,
                                                             zQ, 4 * HQ, 0);
        }
        lstm_gate_kernel<<<(BB * HQ) / 256, 256>>>(zQ, hQ, cQ, HQ);

        // LSTM Sigma: input = concat(hQ, out6)
        {
            GSeg a = {hQ,   Wsig_ih,        HQ,     D_SIG_IN};
            GSeg b = {out6, Wsig_ih + HQ,   D_Q_IN, D_SIG_IN};
            GSeg c = {hSig, Wsig_hh,        HQ,     HQ};
            gemm_kernel<<<dim3(4 * HQ / 64, BB / 64), 256>>>(a, b, c, 3, bsig_ih, bsig_hh,
                                                             zSig, 4 * HQ, 0);
        }
        lstm_gate_kernel<<<(BB * HQ) / 256, 256>>>(zSig, hSig, cSig, HQ);

        // fc1: relu(hSig @ fc1_w^T + b)
        {
            GSeg a = {hSig, fc1_w, HQ, HQ};
            gemm_kernel<<<dim3(HS / 64, BB / 64), 256>>>(a, nil, nil, 1, fc1_b, nullptr,
                                                         out1, HS, 1);
        }

        // LSTM S: input = concat(out1, out7)
        {
            GSeg a = {out1, Ws_ih,       HS,     D_S_IN};
            GSeg b = {out7, Ws_ih + HS,  D_Q_IN, D_S_IN};
            GSeg c = {hS,   Ws_hh,       HS,     HS};
            gemm_kernel<<<dim3(4 * HS / 64, BB / 64), 256>>>(a, b, c, 3, bs_ih, bs_hh,
                                                             zS, 4 * HS, 0);
        }
        lstm_gate_kernel<<<(BB * HS) / 256, 256>>>(zS, hS, cS, HS);

        // fc2a: relu(concat(hSig, hS) @ fc2a_w^T + b)
        {
            GSeg a = {hSig, fc2a_w,      HQ, D_FC2_IN};
            GSeg b = {hS,   fc2a_w + HQ, HS, D_FC2_IN};
            gemm_kernel<<<dim3(D_FC2_H / 64, BB / 64), 256>>>(a, b, nil, 2, fc2a_b, nullptr,
                                                              a2, D_FC2_H, 1);
        }

        // fc2b: k_vec = a2 @ fc2b_w^T + b
        {
            GSeg a = {a2, fc2b_w, D_FC2_H, D_FC2_H};
            gemm_kernel<<<dim3(NN * MM / 64, BB / 64), 256>>>(a, nil, nil, 1, fc2b_b, nullptr,
                                                              kvec, NN * MM, 0);
        }

        update_kernel<<<BB, 32>>>(x_prior, kvec, dy, out + (size_t)t * BB * MM);
    }
}

// round 3
// speedup vs baseline: 2.7670x; 2.7670x over previous
#include <cuda_runtime.h>
#include <cuda_bf16.h>
#include <math.h>
#include <stdint.h>

// ---------------- problem constants ----------------
#define MM   32      // state dim m
#define NN   16      // obs dim n
#define BB   256     // batch
#define TT   8       // time steps
#define HQ   1024    // m*m
#define HS   256     // n*n
#define D_Q_IN   160      // m*IN_MULT
#define D_SIG_IN 1184     // HQ + 160
#define D_S_IN   416      // 256 + 160
#define D_FC2_IN 1280     // HQ + HS
#define D_FC2_H  2560

// ---------------- device scratch (no allocations allowed) ----------------
__device__ float g_zQ  [BB * 4 * HQ];
__device__ float g_zSig[BB * 4 * HQ];
__device__ float g_zS  [BB * 4 * HS];
__device__ float g_hQ  [BB * HQ];
__device__ float g_cQ  [BB * HQ];
__device__ float g_hSig[BB * HQ];
__device__ float g_cSig[BB * HQ];
__device__ float g_hS  [BB * HS];
__device__ float g_cS  [BB * HS];
__device__ float g_out5[BB * D_Q_IN];
__device__ float g_out6[BB * D_Q_IN];
__device__ float g_out7[BB * D_Q_IN];
__device__ float g_out1[BB * HS];
__device__ float g_a2  [BB * D_FC2_H];
__device__ float g_kvec[BB * NN * MM];
__device__ float g_xprior[2][BB * MM];
__device__ float g_dy   [BB * NN];
__device__ float g_fwupd [BB * MM];
__device__ float g_fwevol[BB * MM];
__device__ float g_obscat[BB * 2 * NN];
__device__ float g_yprev0[BB * NN];

// ---------------- init ----------------
__global__ void init_kernel(const float* __restrict__ x0,
                            float* __restrict__ yprev0,
                            float* hQ, float* cQ, float* hSig, float* cSig,
                            float* hS, float* cS)
{
    int idx = blockIdx.x * blockDim.x + threadIdx.x;
    if (idx < BB * HQ) { hQ[idx] = 0.f; cQ[idx] = 0.f; hSig[idx] = 0.f; cSig[idx] = 0.f; }
    if (idx < BB * HS) { hS[idx] = 0.f; cS[idx] = 0.f; }
    if (idx < BB * NN) {
        int b = idx / NN, n = idx % NN;
        yprev0[idx] = tanhf(x0[b * MM + n]);
    }
}

// ---------------- per-step prologue ----------------
__global__ void pre_kernel(const float* __restrict__ x_post,
                           const float* __restrict__ x_post_prev,
                           const float* __restrict__ x_prior_prev,
                           const float* __restrict__ y_t,
                           const float* __restrict__ y_prev,
                           float* __restrict__ x_prior,
                           float* __restrict__ dy_buf,
                           float* __restrict__ fw_upd,
                           float* __restrict__ fw_evol,
                           float* __restrict__ obs_cat)
{
    int b = blockIdx.x;
    int lane = threadIdx.x;  // 0..31

    float xp   = x_post[b * MM + lane];
    float xpp  = x_post_prev[b * MM + lane];
    float xprp = x_prior_prev[b * MM + lane];

    float xpr = xp + 0.1f * sinf(xp);          // f_dyn
    x_prior[b * MM + lane] = xpr;

    float de = xp - xpp;
    float du = xp - xprp;
    float se = de * de, su = du * du;
    #pragma unroll
    for (int o = 16; o > 0; o >>= 1) {
        se += __shfl_xor_sync(0xffffffffu, se, o);
        su += __shfl_xor_sync(0xffffffffu, su, o);
    }
    fw_evol[b * MM + lane] = de / fmaxf(sqrtf(se), 1e-12f);
    fw_upd [b * MM + lane] = du / fmaxf(sqrtf(su), 1e-12f);

    float y     = (lane < NN) ? y_t[b * NN + lane]    : 0.f;
    float ypv   = (lane < NN) ? y_prev[b * NN + lane] : 0.f;
    float ypred = (lane < NN) ? tanhf(xpr)            : 0.f;
    float d1 = y - ypv;
    float d2 = y - ypred;
    if (lane < NN) dy_buf[b * NN + lane] = d2;
    float s1 = d1 * d1, s2 = d2 * d2;
    #pragma unroll
    for (int o = 16; o > 0; o >>= 1) {
        s1 += __shfl_xor_sync(0xffffffffu, s1, o);
        s2 += __shfl_xor_sync(0xffffffffu, s2, o);
    }
    if (lane < NN) {
        obs_cat[b * 2 * NN + lane]      = d1 / fmaxf(sqrtf(s1), 1e-12f);
        obs_cat[b * 2 * NN + NN + lane] = d2 / fmaxf(sqrtf(s2), 1e-12f);
    }
}

// ---------------- fused fc5 / fc6 / fc7 ----------------
__global__ void fc_small_kernel(const float* __restrict__ in_upd,
                                const float* __restrict__ in_evol,
                                const float* __restrict__ in_obs,
                                const float* __restrict__ w5, const float* __restrict__ b5,
                                const float* __restrict__ w6, const float* __restrict__ b6,
                                const float* __restrict__ w7, const float* __restrict__ b7,
                                float* __restrict__ out5,
                                float* __restrict__ out6,
                                float* __restrict__ out7)
{
    int which = blockIdx.y;
    const float* X = (which == 0) ? in_upd : (which == 1) ? in_evol : in_obs;
    const float* W = (which == 0) ? w5     : (which == 1) ? w6      : w7;
    const float* Bv= (which == 0) ? b5     : (which == 1) ? b6      : b7;
    float* O       = (which == 0) ? out5   : (which == 1) ? out6    : out7;

    int b = blockIdx.x;
    __shared__ float xs[32];
    if (threadIdx.x < 32) xs[threadIdx.x] = X[b * 32 + threadIdx.x];
    __syncthreads();

    int o = threadIdx.x;  // 0..159
    float acc = Bv[o];
    const float* wr = W + o * 32;
    #pragma unroll
    for (int k = 0; k < 32; k++) acc += xs[k] * wr[k];
    O[b * D_Q_IN + o] = fmaxf(acc, 0.f);
}

// ---------------- TF32 tensor-core multi-segment GEMM ----------------
// Z[b, o] = act( sum_s X_s[b,:] . W_s[o,:] + bias0[o] (+ bias1[o]) )
// Tiles: BM=128 (batch), BN=64 (out), BK=16. 8 warps (4m x 2n), warp = 32x32.
// Requires: every segment K % 16 == 0, Nout % 64 == 0, BB % 128 == 0. (All hold.)
struct GSeg {
    const float* X;   // [BB, K] contiguous
    const float* W;   // row-major, row stride ldw
    int K;
    int ldw;
};

#define LDA 20   // padded smem stride (floats) — conflict-free fragment reads

__device__ __forceinline__ void cpa16(void* s, const void* g) {
    uint32_t sa = (uint32_t)__cvta_generic_to_shared(s);
    asm volatile("cp.async.cg.shared.global [%0], [%1], 16;\n" :: "r"(sa), "l"(g));
}
__device__ __forceinline__ uint32_t f2tf32(float f) {
    uint32_t u;
    asm("cvt.rna.tf32.f32 %0, %1;" : "=r"(u) : "f"(f));
    return u;
}

__global__ void __launch_bounds__(256) gemm_tc(
    GSeg s0, GSeg s1, GSeg s2, int nseg,
    const float* __restrict__ bias0, const float* __restrict__ bias1,
    float* __restrict__ Z, int Nout, int act)
{
    __shared__ float As[2][128 * LDA];
    __shared__ float Bs[2][64 * LDA];

    int tid  = threadIdx.x;
    int lane = tid & 31;
    int wid  = tid >> 5;
    int wm   = wid & 3;      // warp row (0..3)
    int wn   = wid >> 2;     // warp col (0..1)
    int gid  = lane >> 2;    // 0..7
    int tg   = lane & 3;     // 0..3

    int row0 = blockIdx.y * 128;
    int col0 = blockIdx.x * 64;

    // per-thread staging coords
    int arow = tid >> 2;          // 0..63 (and +64)
    int acol = (tid & 3) * 4;     // 0,4,8,12
    int brow = tid >> 2;          // 0..63
    int bcol = (tid & 3) * 4;

    int totK = s0.K + ((nseg > 1) ? s1.K : 0) + ((nseg > 2) ? s2.K : 0);
    int niter = totK >> 4;

    float c[2][4][4];
    #pragma unroll
    for (int mt = 0; mt < 2; mt++)
        #pragma unroll
        for (int nt = 0; nt < 4; nt++)
            #pragma unroll
            for (int r = 0; r < 4; r++) c[mt][nt][r] = 0.f;

    // ---- async load of iteration `it` into buffer p ----
    auto issue = [&](int it, int p) {
        int kb = it << 4;
        const float* X = s0.X; const float* W = s0.W; int K = s0.K; int ldw = s0.ldw;
        if (kb >= s0.K) {
            kb -= s0.K;
            if (nseg > 2 && kb >= s1.K) { kb -= s1.K; X = s2.X; W = s2.W; K = s2.K; ldw = s2.ldw; }
            else                        {             X = s1.X; W = s1.W; K = s1.K; ldw = s1.ldw; }
        }
        const float* xsrc = X + (size_t)(row0 + arow) * K + kb + acol;
        cpa16(&As[p][arow * LDA + acol],        xsrc);
        cpa16(&As[p][(arow + 64) * LDA + acol], xsrc + (size_t)64 * K);
        cpa16(&Bs[p][brow * LDA + bcol],
              W + (size_t)(col0 + brow) * ldw + kb + bcol);
        asm volatile("cp.async.commit_group;\n" ::);
    };

    issue(0, 0);

    for (int it = 0; it < niter; it++) {
        int p = it & 1;
        if (it + 1 < niter) {
            issue(it + 1, p ^ 1);
            asm volatile("cp.async.wait_group 1;\n" ::);
        } else {
            asm volatile("cp.async.wait_group 0;\n" ::);
        }
        __syncthreads();

        #pragma unroll
        for (int ks = 0; ks < 2; ks++) {
            int kk = ks * 8;
            uint32_t af[2][4];
            #pragma unroll
            for (int mt = 0; mt < 2; mt++) {
                int r = wm * 32 + mt * 16 + gid;
                af[mt][0] = f2tf32(As[p][r * LDA + kk + tg]);
                af[mt][1] = f2tf32(As[p][(r + 8) * LDA + kk + tg]);
                af[mt][2] = f2tf32(As[p][r * LDA + kk + tg + 4]);
                af[mt][3] = f2tf32(As[p][(r + 8) * LDA + kk + tg + 4]);
            }
            uint32_t bf[4][2];
            #pragma unroll
            for (int nt = 0; nt < 4; nt++) {
                int n = wn * 32 + nt * 8 + gid;
                bf[nt][0] = f2tf32(Bs[p][n * LDA + kk + tg]);
                bf[nt][1] = f2tf32(Bs[p][n * LDA + kk + tg + 4]);
            }
            #pragma unroll
            for (int mt = 0; mt < 2; mt++)
                #pragma unroll
                for (int nt = 0; nt < 4; nt++) {
                    asm volatile(
                        "mma.sync.aligned.m16n8k8.row.col.f32.tf32.tf32.f32 "
                        "{%0,%1,%2,%3}, {%4,%5,%6,%7}, {%8,%9}, {%0,%1,%2,%3};\n"
                        : "+f"(c[mt][nt][0]), "+f"(c[mt][nt][1]),
                          "+f"(c[mt][nt][2]), "+f"(c[mt][nt][3])
                        : "r"(af[mt][0]), "r"(af[mt][1]), "r"(af[mt][2]), "r"(af[mt][3]),
                          "r"(bf[nt][0]), "r"(bf[nt][1]));
                }
        }
        __syncthreads();
    }

    // ---- epilogue: bias (+bias1) (+relu), float2 stores ----
    #pragma unroll
    for (int mt = 0; mt < 2; mt++) {
        int r = row0 + wm * 32 + mt * 16 + gid;
        #pragma unroll
        for (int nt = 0; nt < 4; nt++) {
            int cb = col0 + wn * 32 + nt * 8 + tg * 2;
            float b0a = bias0[cb], b0b = bias0[cb + 1];
            if (bias1) { b0a += bias1[cb]; b0b += bias1[cb + 1]; }
            float v0 = c[mt][nt][0] + b0a;
            float v1 = c[mt][nt][1] + b0b;
            float v2 = c[mt][nt][2] + b0a;
            float v3 = c[mt][nt][3] + b0b;
            if (act) {
                v0 = fmaxf(v0, 0.f); v1 = fmaxf(v1, 0.f);
                v2 = fmaxf(v2, 0.f); v3 = fmaxf(v3, 0.f);
            }
            *reinterpret_cast<float2*>(&Z[(size_t)r * Nout + cb])       = make_float2(v0, v1);
            *reinterpret_cast<float2*>(&Z[(size_t)(r + 8) * Nout + cb]) = make_float2(v2, v3);
        }
    }
}

// ---------------- LSTM pointwise gates (torch order i,f,g,o) ----------------
__global__ void lstm_gate_kernel(const float* __restrict__ Z,
                                 float* __restrict__ h, float* __restrict__ c, int H)
{
    int idx = blockIdx.x * blockDim.x + threadIdx.x;
    if (idx >= BB * H) return;
    int b = idx / H, j = idx % H;
    const float* z = Z + (size_t)b * 4 * H;
    float gi = z[j], gf = z[H + j], gg = z[2 * H + j], go = z[3 * H + j];
    float si = 1.f / (1.f + expf(-gi));
    float sf = 1.f / (1.f + expf(-gf));
    float so = 1.f / (1.f + expf(-go));
    float cn = sf * c[idx] + si * tanhf(gg);
    c[idx] = cn;
    h[idx] = so * tanhf(cn);
}

// ---------------- KF update: x_post = x_prior + K @ dy ----------------
__global__ void update_kernel(const float* __restrict__ x_prior,
                              const float* __restrict__ kvec,
                              const float* __restrict__ dy,
                              float* __restrict__ out)
{
    int b = blockIdx.x;
    int m = threadIdx.x;
    __shared__ float dys[NN];
    if (m < NN) dys[m] = dy[b * NN + m];
    __syncthreads();
    float acc = x_prior[b * MM + m];
    const float* Kr = kvec + (size_t)b * MM * NN + m * NN;
    #pragma unroll
    for (int n = 0; n < NN; n++) acc += Kr[n] * dys[n];
    out[b * MM + m] = acc;
}

// ---------------- host orchestration ----------------
extern "C" void kernel_launch(void* const* d_in, const int* in_sizes, int n_in,
                              void* d_out, int out_size)
{
    const float* Y       = (const float*)d_in[0];
    const float* x0      = (const float*)d_in[1];
    const float* Wq_ih   = (const float*)d_in[2];
    const float* Wq_hh   = (const float*)d_in[3];
    const float* bq_ih   = (const float*)d_in[4];
    const float* bq_hh   = (const float*)d_in[5];
    const float* Wsig_ih = (const float*)d_in[6];
    const float* Wsig_hh = (const float*)d_in[7];
    const float* bsig_ih = (const float*)d_in[8];
    const float* bsig_hh = (const float*)d_in[9];
    const float* Ws_ih   = (const float*)d_in[10];
    const float* Ws_hh   = (const float*)d_in[11];
    const float* bs_ih   = (const float*)d_in[12];
    const float* bs_hh   = (const float*)d_in[13];
    const float* fc1_w   = (const float*)d_in[14];
    const float* fc1_b   = (const float*)d_in[15];
    const float* fc2a_w  = (const float*)d_in[16];
    const float* fc2a_b  = (const float*)d_in[17];
    const float* fc2b_w  = (const float*)d_in[18];
    const float* fc2b_b  = (const float*)d_in[19];
    const float* fc5_w   = (const float*)d_in[20];
    const float* fc5_b   = (const float*)d_in[21];
    const float* fc6_w   = (const float*)d_in[22];
    const float* fc6_b   = (const float*)d_in[23];
    const float* fc7_w   = (const float*)d_in[24];
    const float* fc7_b   = (const float*)d_in[25];

    float* out = (float*)d_out;   // [T, B, M, 1]

    float *zQ, *zSig, *zS, *hQ, *cQ, *hSig, *cSig, *hS, *cS;
    float *out5, *out6, *out7, *out1, *a2, *kvec;
    float *xprior0, *xprior1, *dy, *fwupd, *fwevol, *obscat, *yprev0;
    cudaGetSymbolAddress((void**)&zQ,    g_zQ);
    cudaGetSymbolAddress((void**)&zSig,  g_zSig);
    cudaGetSymbolAddress((void**)&zS,    g_zS);
    cudaGetSymbolAddress((void**)&hQ,    g_hQ);
    cudaGetSymbolAddress((void**)&cQ,    g_cQ);
    cudaGetSymbolAddress((void**)&hSig,  g_hSig);
    cudaGetSymbolAddress((void**)&cSig,  g_cSig);
    cudaGetSymbolAddress((void**)&hS,    g_hS);
    cudaGetSymbolAddress((void**)&cS,    g_cS);
    cudaGetSymbolAddress((void**)&out5,  g_out5);
    cudaGetSymbolAddress((void**)&out6,  g_out6);
    cudaGetSymbolAddress((void**)&out7,  g_out7);
    cudaGetSymbolAddress((void**)&out1,  g_out1);
    cudaGetSymbolAddress((void**)&a2,    g_a2);
    cudaGetSymbolAddress((void**)&kvec,  g_kvec);
    cudaGetSymbolAddress((void**)&xprior0, g_xprior);
    xprior1 = xprior0 + BB * MM;
    cudaGetSymbolAddress((void**)&dy,    g_dy);
    cudaGetSymbolAddress((void**)&fwupd, g_fwupd);
    cudaGetSymbolAddress((void**)&fwevol,g_fwevol);
    cudaGetSymbolAddress((void**)&obscat,g_obscat);
    cudaGetSymbolAddress((void**)&yprev0,g_yprev0);

    float* xprior_buf[2] = {xprior0, xprior1};

    const GSeg nil = {nullptr, nullptr, 0, 0};

    init_kernel<<<(BB * HQ + 255) / 256, 256>>>(x0, yprev0, hQ, cQ, hSig, cSig, hS, cS);

    for (int t = 0; t < TT; t++) {
        const float* x_post      = (t == 0) ? x0 : out + (size_t)(t - 1) * BB * MM;
        const float* x_post_prev = (t <= 1) ? x0 : out + (size_t)(t - 2) * BB * MM;
        const float* x_prior_prev= (t == 0) ? x0 : xprior_buf[(t - 1) & 1];
        const float* y_t         = Y + (size_t)t * BB * NN;
        const float* y_prev      = (t == 0) ? yprev0 : Y + (size_t)(t - 1) * BB * NN;
        float* x_prior           = xprior_buf[t & 1];

        pre_kernel<<<BB, 32>>>(x_post, x_post_prev, x_prior_prev, y_t, y_prev,
                               x_prior, dy, fwupd, fwevol, obscat);

        fc_small_kernel<<<dim3(BB, 3), 160>>>(fwupd, fwevol, obscat,
                                              fc5_w, fc5_b, fc6_w, fc6_b, fc7_w, fc7_b,
                                              out5, out6, out7);

        // LSTM Q
        {
            GSeg a = {out5, Wq_ih, D_Q_IN, D_Q_IN};
            GSeg b = {hQ,   Wq_hh, HQ,     HQ};
            gemm_tc<<<dim3(4 * HQ / 64, BB / 128), 256>>>(a, b, nil, 2, bq_ih, bq_hh,
                                                          zQ, 4 * HQ, 0);
        }
        lstm_gate_kernel<<<(BB * HQ) / 256, 256>>>(zQ, hQ, cQ, HQ);

        // LSTM Sigma: input = concat(hQ, out6)
        {
            GSeg a = {hQ,   Wsig_ih,        HQ,     D_SIG_IN};
            GSeg b = {out6, Wsig_ih + HQ,   D_Q_IN, D_SIG_IN};
            GSeg c = {hSig, Wsig_hh,        HQ,     HQ};
            gemm_tc<<<dim3(4 * HQ / 64, BB / 128), 256>>>(a, b, c, 3, bsig_ih, bsig_hh,
                                                          zSig, 4 * HQ, 0);
        }
        lstm_gate_kernel<<<(BB * HQ) / 256, 256>>>(zSig, hSig, cSig, HQ);

        // fc1
        {
            GSeg a = {hSig, fc1_w, HQ, HQ};
            gemm_tc<<<dim3(HS / 64, BB / 128), 256>>>(a, nil, nil, 1, fc1_b, nullptr,
                                                      out1, HS, 1);
        }

        // LSTM S: input = concat(out1, out7)
        {
            GSeg a = {out1, Ws_ih,       HS,     D_S_IN};
            GSeg b = {out7, Ws_ih + HS,  D_Q_IN, D_S_IN};
            GSeg c = {hS,   Ws_hh,       HS,     HS};
            gemm_tc<<<dim3(4 * HS / 64, BB / 128), 256>>>(a, b, c, 3, bs_ih, bs_hh,
                                                          zS, 4 * HS, 0);
        }
        lstm_gate_kernel<<<(BB * HS) / 256, 256>>>(zS, hS, cS, HS);

        // fc2a
        {
            GSeg a = {hSig, fc2a_w,      HQ, D_FC2_IN};
            GSeg b = {hS,   fc2a_w + HQ, HS, D_FC2_IN};
            gemm_tc<<<dim3(D_FC2_H / 64, BB / 128), 256>>>(a, b, nil, 2, fc2a_b, nullptr,
                                                           a2, D_FC2_H, 1);
        }

        // fc2b
        {
            GSeg a = {a2, fc2b_w, D_FC2_H, D_FC2_H};
            gemm_tc<<<dim3(NN * MM / 64, BB / 128), 256>>>(a, nil, nil, 1, fc2b_b, nullptr,
                                                           kvec, NN * MM, 0);
        }

        update_kernel<<<BB, 32>>>(x_prior, kvec, dy, out + (size_t)t * BB * MM);
    }
}